// round 15
// baseline (speedup 1.0000x reference)
#include <cuda_runtime.h>
#include <cuda_fp16.h>
#include <cstdint>

// ---------------- problem constants ----------------
#define PLM   768
#define GG    256
#define NWM   50000
#define EWM   800000
#define NF    16384           // B*S
#define EF    131072
#define KSLOT 4
#define G4    (GG/4)          // 64 float4 per G-row
#define PLM4  (PLM/4)         // 192 float4 per PLM-row
#define CAT3  (PLM + 2*GG)    // 1280
#define CAT1  (GG + PLM)      // 1024

// ---------------- device scratch (no runtime alloc allowed) ----------------
__device__ __align__(16) float g_zerob[PLM];               // zero bias (BSS)
// fp16 buffers (all GEMMs plain fp16, 1-pass)
__device__ __align__(16) __half g_th [(size_t)NWM * GG];   // t = h @ W (WM + FSTM reuse)
__device__ __align__(16) __half g_geh[(size_t)NWM * GG];   // graph embeddings
__device__ __align__(16) __half g_ah [(size_t)NWM * GG];   // activations
__device__ __align__(16) __half g_gteh[(size_t)NF * GG];   // graph_text_embed
__device__ __align__(16) __half g_c1h[(size_t)NF * CAT1];
__device__ __align__(16) __half g_c3h[(size_t)NF * CAT3];
// fp16 transposed weights [N, K]
__device__ __align__(16) __half g_w1h[GG * GG];
__device__ __align__(16) __half g_w2h[GG * GG];
__device__ __align__(16) __half g_g1h[GG * GG];
__device__ __align__(16) __half g_g2h[GG * GG];
__device__ __align__(16) __half g_fc1h[GG * CAT1];
__device__ __align__(16) __half g_fc3h[PLM * CAT3];
// CSR
__device__ int g_wm_rowptr[NWM + 1];
__device__ int g_wm_cur[NWM];
__device__ int g_wm_col[EWM];
__device__ int g_f_rowptr[NF + 1];
__device__ int g_f_cur[NF];
__device__ int g_f_col[EF];

// ---------------- helpers ----------------
__device__ __forceinline__ uint32_t smem_u32(const void* p) {
    uint32_t a;
    asm("{ .reg .u64 t; cvta.to.shared.u64 t, %1; cvt.u32.u64 %0, t; }" : "=r"(a) : "l"(p));
    return a;
}
__device__ __forceinline__ void cp16(uint32_t dst, const void* src, uint32_t srcsize) {
    asm volatile("cp.async.cg.shared.global [%0], [%1], 16, %2;"
                 :: "r"(dst), "l"(src), "r"(srcsize) : "memory");
}
#define CP_COMMIT() asm volatile("cp.async.commit_group;" ::: "memory")
#define CP_WAIT(n)  asm volatile("cp.async.wait_group %0;" :: "n"(n) : "memory")

__device__ __forceinline__ void ldsm4(uint32_t* r, uint32_t addr) {
    asm volatile("ldmatrix.sync.aligned.m8n8.x4.shared.b16 {%0,%1,%2,%3}, [%4];"
                 : "=r"(r[0]), "=r"(r[1]), "=r"(r[2]), "=r"(r[3]) : "r"(addr));
}
__device__ __forceinline__ void mma16816(float* c, const uint32_t* a, uint32_t b0, uint32_t b1) {
    asm volatile(
        "mma.sync.aligned.m16n8k16.row.col.f32.f16.f16.f32 "
        "{%0,%1,%2,%3}, {%4,%5,%6,%7}, {%8,%9}, {%0,%1,%2,%3};\n"
        : "+f"(c[0]), "+f"(c[1]), "+f"(c[2]), "+f"(c[3])
        : "r"(a[0]), "r"(a[1]), "r"(a[2]), "r"(a[3]), "r"(b0), "r"(b1));
}

__device__ __forceinline__ uint32_t packh(float a, float b) {
    __half ha = __float2half_rn(a), hb = __float2half_rn(b);
    return ((uint32_t)__half_as_ushort(hb) << 16) | (uint32_t)__half_as_ushort(ha);
}
__device__ __forceinline__ uint2 pack4h(float4 v) {
    uint2 hp;
    hp.x = packh(v.x, v.y);
    hp.y = packh(v.z, v.w);
    return hp;
}
__device__ __forceinline__ float4 h4_to_f4(uint2 u) {
    __half2 a = *(__half2*)&u.x, b = *(__half2*)&u.y;
    float2 fa = __half22float2(a), fb = __half22float2(b);
    return make_float4(fa.x, fa.y, fb.x, fb.y);
}

// ---------------- fused CSR build kernels (both graphs per launch) ----------------
__global__ void zero_both_kernel(int* __restrict__ p1, int* __restrict__ p2) {
    int i = blockIdx.x * blockDim.x + threadIdx.x;
    if (i < NWM) p1[i] = 0;
    else if (i < NWM + NF) p2[i - NWM] = 0;
}
__global__ void hist_both_kernel(const int* __restrict__ dstW, int* __restrict__ cntW,
                                 const int* __restrict__ dstF, int* __restrict__ cntF) {
    int e = blockIdx.x * blockDim.x + threadIdx.x;
    if (e < EWM) atomicAdd(&cntW[dstW[e]], 1);
    else if (e < EWM + EF) atomicAdd(&cntF[dstF[e - EWM]], 1);
}
// 2 blocks: block 0 -> WM, block 1 -> FSTM
__global__ void scan_both_kernel(int* __restrict__ cntW, int* __restrict__ rpW,
                                 int* __restrict__ cntF, int* __restrict__ rpF) {
    __shared__ int sh[1024];
    int* cnt_cur = blockIdx.x == 0 ? cntW : cntF;
    int* rowptr  = blockIdx.x == 0 ? rpW  : rpF;
    const int N  = blockIdx.x == 0 ? NWM : NF;
    const int E  = blockIdx.x == 0 ? EWM : EF;
    int tid = threadIdx.x;
    int chunk = (N + 1023) >> 10;
    int s0 = tid * chunk;
    int s1 = s0 + chunk; if (s1 > N) s1 = N;
    int s = 0;
    for (int i = s0; i < s1; i++) s += cnt_cur[i];
    sh[tid] = s;
    __syncthreads();
    for (int off = 1; off < 1024; off <<= 1) {
        int v = (tid >= off) ? sh[tid - off] : 0;
        __syncthreads();
        sh[tid] += v;
        __syncthreads();
    }
    int run = sh[tid] - s;
    for (int i = s0; i < s1; i++) {
        int c = cnt_cur[i];
        rowptr[i]  = run;
        cnt_cur[i] = run;
        run += c;
    }
    if (tid == 0) rowptr[N] = E;
}
__global__ void fill_both_kernel(const int* __restrict__ srcW, const int* __restrict__ dstW,
                                 int* __restrict__ curW, int* __restrict__ colW,
                                 const int* __restrict__ srcF, const int* __restrict__ dstF,
                                 int* __restrict__ curF, int* __restrict__ colF) {
    int e = blockIdx.x * blockDim.x + threadIdx.x;
    if (e < EWM) {
        int d = dstW[e];
        int p = atomicAdd(&curW[d], 1);
        colW[p] = srcW[e];
    } else if (e < EWM + EF) {
        int e2 = e - EWM;
        int d = dstF[e2];
        int p = atomicAdd(&curF[d], 1);
        colF[p] = srcF[e2];
    }
}

// ---------------- elementwise / gather kernels ----------------
__global__ void split_x_hi_kernel(const float4* __restrict__ x,
                                  __half* __restrict__ oh, int n4) {
    int idx = blockIdx.x * blockDim.x + threadIdx.x;
    if (idx >= n4) return;
    *(uint2*)(oh + 4 * (size_t)idx) = pack4h(x[idx]);
}

// fp16-t aggregation: v = relu(t[n] + sum t[src] + bias); write fp16 (strided)
__global__ void spmm_post_h16_kernel(const uint2* __restrict__ t,
                                     const int* __restrict__ rowptr,
                                     const int* __restrict__ col,
                                     const float* __restrict__ bias,
                                     __half* __restrict__ oh,
                                     size_t ldo, size_t coff, int n) {
    int node = blockIdx.x * blockDim.y + threadIdx.y;
    if (node >= n) return;
    int x = threadIdx.x;  // 0..63 (uint2 = 4 halves)
    float4 acc = h4_to_f4(t[(size_t)node * 64 + x]);
    int e  = rowptr[node];
    int e1 = rowptr[node + 1];
    for (; e + 4 <= e1; e += 4) {
        int s0 = __ldg(&col[e]), s1 = __ldg(&col[e + 1]);
        int s2 = __ldg(&col[e + 2]), s3 = __ldg(&col[e + 3]);
        float4 v0 = h4_to_f4(__ldg(&t[(size_t)s0 * 64 + x]));
        float4 v1 = h4_to_f4(__ldg(&t[(size_t)s1 * 64 + x]));
        float4 v2 = h4_to_f4(__ldg(&t[(size_t)s2 * 64 + x]));
        float4 v3 = h4_to_f4(__ldg(&t[(size_t)s3 * 64 + x]));
        acc.x += v0.x + v1.x + v2.x + v3.x;
        acc.y += v0.y + v1.y + v2.y + v3.y;
        acc.z += v0.z + v1.z + v2.z + v3.z;
        acc.w += v0.w + v1.w + v2.w + v3.w;
    }
    for (; e < e1; ++e) {
        int s = __ldg(&col[e]);
        float4 v = h4_to_f4(__ldg(&t[(size_t)s * 64 + x]));
        acc.x += v.x; acc.y += v.y; acc.z += v.z; acc.w += v.w;
    }
    float4 bv = *(const float4*)&bias[4 * x];
    acc.x = fmaxf(acc.x + bv.x, 0.f);
    acc.y = fmaxf(acc.y + bv.y, 0.f);
    acc.z = fmaxf(acc.z + bv.z, 0.f);
    acc.w = fmaxf(acc.w + bv.w, 0.f);
    *(uint2*)(oh + (size_t)node * ldo + coff + 4 * x) = pack4h(acc);
}

// tmp[row] = sum_k ge16[t2n[row*4+k]]; fp16 into cat1 @col0 and cat3 @col768
__global__ void gather4sum_h_kernel(const uint2* __restrict__ ge,
                                    const int* __restrict__ t2n,
                                    __half* __restrict__ c1h,
                                    __half* __restrict__ c3h, int rows) {
    int row = blockIdx.x * blockDim.y + threadIdx.y;
    if (row >= rows) return;
    int x = threadIdx.x;
    float4 acc = make_float4(0.f, 0.f, 0.f, 0.f);
#pragma unroll
    for (int k = 0; k < KSLOT; k++) {
        int idx = __ldg(&t2n[row * KSLOT + k]);
        float4 v = h4_to_f4(__ldg(&ge[(size_t)idx * 64 + x]));
        acc.x += v.x; acc.y += v.y; acc.z += v.z; acc.w += v.w;
    }
    uint2 hp = pack4h(acc);
    *(uint2*)(c1h + (size_t)row * CAT1 + 4 * x) = hp;
    *(uint2*)(c3h + (size_t)row * CAT3 + PLM + 4 * x) = hp;
}

// text fp32 -> fp16 into cat1 @col 256 and cat3 @col 0
__global__ void textconv_kernel(const float4* __restrict__ text,
                                __half* __restrict__ c1h,
                                __half* __restrict__ c3h, int rows) {
    int idx = blockIdx.x * blockDim.x + threadIdx.x;
    if (idx >= rows * PLM4) return;
    int row = idx / PLM4;
    int c   = idx - row * PLM4;
    uint2 hp = pack4h(text[idx]);
    *(uint2*)(c1h + (size_t)row * CAT1 + GG + 4 * c) = hp;
    *(uint2*)(c3h + (size_t)row * CAT3 + 4 * c) = hp;
}

// all weights [K,N] fp32 -> transposed [N,K] fp16 in ONE launch (grid.z selects)
struct WDesc { const float* W; __half* Wh; int Kd; int Nd; };
struct WDescPack { WDesc d[6]; };
__global__ void wconv_all_kernel(WDescPack pack) {
    __shared__ float t[32][33];
    const WDesc& w = pack.d[blockIdx.z];
    int kb = blockIdx.y * 32, nb = blockIdx.x * 32;
    if (kb >= w.Kd || nb >= w.Nd) return;
#pragma unroll
    for (int j = 0; j < 32; j += 8) {
        int k = kb + threadIdx.y + j, n = nb + threadIdx.x;
        t[threadIdx.y + j][threadIdx.x] = w.W[(size_t)k * w.Nd + n];
    }
    __syncthreads();
#pragma unroll
    for (int j = 0; j < 32; j += 8) {
        int n = nb + threadIdx.y + j, k = kb + threadIdx.x;
        w.Wh[(size_t)n * w.Kd + k] = __float2half_rn(t[threadIdx.x][threadIdx.y + j]);
    }
}

// ---------------- legacy-MMA fp16 GEMM (1-pass, 4-stage, 128x64 tile, 3 CTA/SM) ----------------
// D[M,N] = A[Aidx] @ B^T + bias. A: [*,K] fp16 K-major, B: [N,K] fp16 K-major.
// CTA tile 128x64, 8 warps (4m x 2n), warp tile 32x32 (32 acc regs), BK=32,
// 4-stage cp.async, ldmatrix, 3 CTAs/SM (24 warps, 37.5% occ). N%64==0, K%32==0.
#define RS      80
#define TILEA   (128 * RS)           // 10240
#define TILEB2  (64 * RS)            // 5120
#define STAGEB  (TILEA + TILEB2)     // 15360
#define NSTAGE  4
#define GEMM_SMEM (NSTAGE * STAGEB)  // 61440

__global__ __launch_bounds__(256, 3)
void mgemm_kernel(const __half* __restrict__ Ah,
                  const __half* __restrict__ Bh,
                  const float* __restrict__ bias,
                  float* __restrict__ Cf, __half* __restrict__ Ch,
                  const int* __restrict__ Aidx,
                  int ldc, int M, int N, int K) {
    extern __shared__ char smem[];
    const uint32_t sb = smem_u32(smem);
    const int tid = threadIdx.x, lane = tid & 31, wid = tid >> 5;
    const int wm = wid & 3, wn = wid >> 2;         // 4m x 2n warps
    const int bm = blockIdx.y * 128, bn = blockIdx.x * 64;
    const int g = lane >> 2, tg = lane & 3;

    // staging: all threads stage A (128 rows x 64B), threads <128 stage B (64 rows x 64B)
    const int srow = tid >> 1;                     // A row 0..127
    const int hsel = tid & 1;                      // which 32B half of the 64B row
    const int arow = bm + srow;
    const bool aok = arow < M;
    int arA = aok ? arow : 0;
    if (Aidx) arA = __ldg(&Aidx[arA]);
    const uint32_t asz = aok ? 16u : 0u;
    const int brow = bn + (srow & 63);             // B row 0..63 (tid<128)
    const uint32_t adoff = srow * RS + hsel * 32;
    const uint32_t bdoff = (srow & 63) * RS + hsel * 32;

    auto stage = [&](int kt, int b) {
        const size_t ko = (size_t)kt * 32 + hsel * 16;
        const __half* pA = Ah + (size_t)arA * K + ko;
        const uint32_t abase = sb + b * STAGEB + adoff;
        cp16(abase,      pA,     asz);
        cp16(abase + 16, pA + 8, asz);
        if (tid < 128) {
            const __half* pB = Bh + (size_t)brow * K + ko;
            const uint32_t bbase = sb + b * STAGEB + TILEA + bdoff;
            cp16(bbase,      pB,     16u);
            cp16(bbase + 16, pB + 8, 16u);
        }
    };

    const uint32_t aro = (wm * 32 + (lane & 7) + ((lane >> 3) & 1) * 8) * RS;
    const uint32_t ako = ((lane >> 4) & 1) * 16;
    const uint32_t bro = (wn * 32 + (lane & 7) + ((lane >> 4) & 1) * 8) * RS;
    const uint32_t bko = ((lane >> 3) & 1) * 16;

    float acc[2][4][4];
#pragma unroll
    for (int i = 0; i < 2; i++)
#pragma unroll
        for (int j = 0; j < 4; j++)
#pragma unroll
            for (int q = 0; q < 4; q++) acc[i][j][q] = 0.f;

    const int nk = K >> 5;   // >= 8 for all call sites
    stage(0, 0); CP_COMMIT();
    stage(1, 1); CP_COMMIT();
    stage(2, 2); CP_COMMIT();

    int b = 0;
    for (int t = 0; t < nk; t++) {
        const int rem = nk - 1 - t;
        if (rem >= 2)      { CP_WAIT(2); }
        else if (rem == 1) { CP_WAIT(1); }
        else               { CP_WAIT(0); }
        __syncthreads();
        // stage t+3 into buffer (t+3)%4 == (t-1)%4 (computed at iter t-1; safe past barrier)
        if (t + 3 < nk) {
            int nb3 = b + 3; if (nb3 >= NSTAGE) nb3 -= NSTAGE;
            stage(t + 3, nb3);
            CP_COMMIT();
        }

        const uint32_t baseA = sb + b * STAGEB;
        const uint32_t baseB = sb + b * STAGEB + TILEA;

#pragma unroll
        for (int s = 0; s < 2; s++) {
            const uint32_t kb = s * 32;
            uint32_t af[2][4], bf[4][2];
#pragma unroll
            for (int mt = 0; mt < 2; mt++)
                ldsm4(af[mt], baseA + aro + mt * (16 * RS) + kb + ako);
#pragma unroll
            for (int p = 0; p < 2; p++) {
                uint32_t r[4];
                ldsm4(r, baseB + bro + p * (16 * RS) + kb + bko);
                bf[2 * p][0] = r[0]; bf[2 * p][1] = r[1];
                bf[2 * p + 1][0] = r[2]; bf[2 * p + 1][1] = r[3];
            }
#pragma unroll
            for (int nt = 0; nt < 4; nt++)
#pragma unroll
                for (int mt = 0; mt < 2; mt++)
                    mma16816(acc[mt][nt], af[mt], bf[nt][0], bf[nt][1]);
        }
        if (++b == NSTAGE) b = 0;
    }

    // ---- epilogue ----
#pragma unroll
    for (int nt = 0; nt < 4; nt++) {
        const int col = bn + wn * 32 + nt * 8 + 2 * tg;
        float2 bv = *(const float2*)&bias[col];
#pragma unroll
        for (int mt = 0; mt < 2; mt++) {
            const int row0 = bm + wm * 32 + mt * 16 + g;
            float v0 = acc[mt][nt][0] + bv.x;
            float v1 = acc[mt][nt][1] + bv.y;
            float v2 = acc[mt][nt][2] + bv.x;
            float v3 = acc[mt][nt][3] + bv.y;
            if (Ch) {
                if (row0 < M)
                    *(uint32_t*)(Ch + (size_t)row0 * ldc + col) = packh(v0, v1);
                if (row0 + 8 < M)
                    *(uint32_t*)(Ch + (size_t)(row0 + 8) * ldc + col) = packh(v2, v3);
            } else {
                if (row0 < M)
                    *(float2*)&Cf[(size_t)row0 * ldc + col] = make_float2(v0, v1);
                if (row0 + 8 < M)
                    *(float2*)&Cf[(size_t)(row0 + 8) * ldc + col] = make_float2(v2, v3);
            }
        }
    }
}

// ---------------- host launcher ----------------
static void mgemm(const __half* Ah, const __half* Bh, const float* bias,
                  float* Cf, __half* Ch, const int* Aidx,
                  int ldc, int M, int N, int K) {
    dim3 grid(N / 64, (M + 127) / 128);
    mgemm_kernel<<<grid, 256, GEMM_SMEM>>>(Ah, Bh, bias, Cf, Ch, Aidx, ldc, M, N, K);
}

extern "C" void kernel_launch(void* const* d_in, const int* in_sizes, int n_in,
                              void* d_out, int out_size) {
    (void)in_sizes; (void)n_in; (void)out_size;

    const float* text   = (const float*)d_in[0];
    const float* wm_x   = (const float*)d_in[1];
    const int*   wm_ei  = (const int*)  d_in[2];
    const int*   t2n    = (const int*)  d_in[3];
    const int*   fids   = (const int*)  d_in[4];
    const int*   f_ei   = (const int*)  d_in[5];
    // d_in[6] extra_emb: unreachable (indices always >= 2)
    const float* wm_W1  = (const float*)d_in[7];
    const float* wm_b1  = (const float*)d_in[8];
    const float* wm_W2  = (const float*)d_in[9];
    const float* wm_b2  = (const float*)d_in[10];
    const float* f_W1   = (const float*)d_in[11];
    const float* f_b1   = (const float*)d_in[12];
    const float* f_W2   = (const float*)d_in[13];
    const float* f_b2   = (const float*)d_in[14];
    const float* fc1_W  = (const float*)d_in[15];
    const float* fc1_b  = (const float*)d_in[16];
    const float* fc3_W  = (const float*)d_in[17];
    const float* fc3_b  = (const float*)d_in[18];
    float* out = (float*)d_out;

    cudaFuncSetAttribute(mgemm_kernel, cudaFuncAttributeMaxDynamicSharedMemorySize, GEMM_SMEM);

    float* zb;
    __half *th, *geh, *ah, *gteh, *c1h, *c3h;
    __half *w1h, *w2h, *gh1, *gh2, *p1h, *p3h;
    int *wrp, *wcur, *wcol, *frp, *fcur, *fcol;
    cudaGetSymbolAddress((void**)&zb,   g_zerob);
    cudaGetSymbolAddress((void**)&th,   g_th);
    cudaGetSymbolAddress((void**)&geh,  g_geh);
    cudaGetSymbolAddress((void**)&ah,   g_ah);
    cudaGetSymbolAddress((void**)&gteh, g_gteh);
    cudaGetSymbolAddress((void**)&c1h,  g_c1h);
    cudaGetSymbolAddress((void**)&c3h,  g_c3h);
    cudaGetSymbolAddress((void**)&w1h,  g_w1h);
    cudaGetSymbolAddress((void**)&w2h,  g_w2h);
    cudaGetSymbolAddress((void**)&gh1,  g_g1h);
    cudaGetSymbolAddress((void**)&gh2,  g_g2h);
    cudaGetSymbolAddress((void**)&p1h,  g_fc1h);
    cudaGetSymbolAddress((void**)&p3h,  g_fc3h);
    cudaGetSymbolAddress((void**)&wrp,  g_wm_rowptr);
    cudaGetSymbolAddress((void**)&wcur, g_wm_cur);
    cudaGetSymbolAddress((void**)&wcol, g_wm_col);
    cudaGetSymbolAddress((void**)&frp,  g_f_rowptr);
    cudaGetSymbolAddress((void**)&fcur, g_f_cur);
    cudaGetSymbolAddress((void**)&fcol, g_f_col);

    const dim3 bSp(64, 4);

    // ===== launch 1: wm_x fp32 -> fp16 =====
    split_x_hi_kernel<<<(NWM * G4 + 255) / 256, 256>>>((const float4*)wm_x, ah, NWM * G4);
    // ===== launch 2: ALL weight conversions (one launch) =====
    {
        WDescPack pack;
        pack.d[0] = { wm_W1, w1h, GG,   GG  };
        pack.d[1] = { wm_W2, w2h, GG,   GG  };
        pack.d[2] = { f_W1,  gh1, GG,   GG  };
        pack.d[3] = { f_W2,  gh2, GG,   GG  };
        pack.d[4] = { fc1_W, p1h, CAT1, GG  };
        pack.d[5] = { fc3_W, p3h, CAT3, PLM };
        wconv_all_kernel<<<dim3(PLM / 32, CAT3 / 32, 6), dim3(32, 8)>>>(pack);
    }
    // ===== launch 3: zero both CSR cursors =====
    zero_both_kernel<<<(NWM + NF + 255) / 256, 256>>>(wcur, fcur);
    // ===== launch 4: WM layer-1 GEMM (ncu profiles 4th launch) =====
    mgemm(ah, w1h, zb, nullptr, th, nullptr, GG, NWM, GG, GG);
    // ===== CSR build (both graphs, fused) =====
    hist_both_kernel<<<(EWM + EF + 255) / 256, 256>>>(wm_ei + EWM, wcur, f_ei + EF, fcur);
    scan_both_kernel<<<2, 1024>>>(wcur, wrp, fcur, frp);
    fill_both_kernel<<<(EWM + EF + 255) / 256, 256>>>(wm_ei, wm_ei + EWM, wcur, wcol,
                                                      f_ei, f_ei + EF, fcur, fcol);
    // ===== WM aggregation + layer 2 =====
    spmm_post_h16_kernel<<<(NWM + 3) / 4, bSp>>>((const uint2*)th, wrp, wcol, wm_b1,
                                                 ah, GG, 0, NWM);
    mgemm(ah, w2h, zb, nullptr, th, nullptr, GG, NWM, GG, GG);
    spmm_post_h16_kernel<<<(NWM + 3) / 4, bSp>>>((const uint2*)th, wrp, wcol, wm_b2,
                                                 geh, GG, 0, NWM);
    // geh = graph_embeddings [NWM, G] fp16

    // ===== token concept sum + text conversion -> cat buffers =====
    gather4sum_h_kernel<<<(NF + 3) / 4, bSp>>>((const uint2*)geh, t2n, c1h, c3h, NF);
    textconv_kernel<<<(NF * PLM4 + 255) / 256, 256>>>((const float4*)text, c1h, c3h, NF);

    // ===== fc1 =====
    mgemm(c1h, p1h, fc1_b, nullptr, gteh, nullptr, GG, NF, GG, CAT1);

    // ===== FSTM layer 1 (A gathered via fids inside GEMM) =====
    mgemm(gteh, gh1, zb, nullptr, th, fids, GG, NF, GG, GG);
    spmm_post_h16_kernel<<<(NF + 3) / 4, bSp>>>((const uint2*)th, frp, fcol, f_b1,
                                                ah, GG, 0, NF);
    // ===== FSTM layer 2 (output straight into cat3 @ col 1024) =====
    mgemm(ah, gh2, zb, nullptr, th, nullptr, GG, NF, GG, GG);
    spmm_post_h16_kernel<<<(NF + 3) / 4, bSp>>>((const uint2*)th, frp, fcol, f_b2,
                                                c3h, CAT3, PLM + GG, NF);

    // ===== fc3 -> out =====
    mgemm(c3h, p3h, fc3_b, out, nullptr, nullptr, PLM, NF, PLM, CAT3);
}

// round 16
// speedup vs baseline: 1.0663x; 1.0663x over previous
#include <cuda_runtime.h>
#include <cuda_fp16.h>
#include <cstdint>

// ---------------- problem constants ----------------
#define PLM   768
#define GG    256
#define NWM   50000
#define EWM   800000
#define NF    16384           // B*S
#define EF    131072
#define KSLOT 4
#define G4    (GG/4)          // 64 float4 per G-row
#define PLM4  (PLM/4)         // 192 float4 per PLM-row
#define CAT3  (PLM + 2*GG)    // 1280
#define CAT1  (GG + PLM)      // 1024

// ---------------- device scratch (no runtime alloc allowed) ----------------
__device__ __align__(16) float g_zerob[PLM];               // zero bias (BSS)
// fp16 buffers (all GEMMs plain fp16, 1-pass)
__device__ __align__(16) __half g_th [(size_t)NWM * GG];   // t = h @ W (WM + FSTM reuse)
__device__ __align__(16) __half g_geh[(size_t)NWM * GG];   // graph embeddings
__device__ __align__(16) __half g_ah [(size_t)NWM * GG];   // activations
__device__ __align__(16) __half g_gteh[(size_t)NF * GG];   // graph_text_embed
__device__ __align__(16) __half g_c1h[(size_t)NF * CAT1];
__device__ __align__(16) __half g_c3h[(size_t)NF * CAT3];
// fp16 transposed weights [N, K]
__device__ __align__(16) __half g_w1h[GG * GG];
__device__ __align__(16) __half g_w2h[GG * GG];
__device__ __align__(16) __half g_g1h[GG * GG];
__device__ __align__(16) __half g_g2h[GG * GG];
__device__ __align__(16) __half g_fc1h[GG * CAT1];
__device__ __align__(16) __half g_fc3h[PLM * CAT3];
// CSR
__device__ int g_wm_rowptr[NWM + 1];
__device__ int g_wm_cur[NWM];
__device__ int g_wm_col[EWM];
__device__ int g_f_rowptr[NF + 1];
__device__ int g_f_cur[NF];
__device__ int g_f_col[EF];

// ---------------- helpers ----------------
__device__ __forceinline__ uint32_t smem_u32(const void* p) {
    uint32_t a;
    asm("{ .reg .u64 t; cvta.to.shared.u64 t, %1; cvt.u32.u64 %0, t; }" : "=r"(a) : "l"(p));
    return a;
}
__device__ __forceinline__ void cp16(uint32_t dst, const void* src, uint32_t srcsize) {
    asm volatile("cp.async.cg.shared.global [%0], [%1], 16, %2;"
                 :: "r"(dst), "l"(src), "r"(srcsize) : "memory");
}
#define CP_COMMIT() asm volatile("cp.async.commit_group;" ::: "memory")
#define CP_WAIT(n)  asm volatile("cp.async.wait_group %0;" :: "n"(n) : "memory")

__device__ __forceinline__ void ldsm4(uint32_t* r, uint32_t addr) {
    asm volatile("ldmatrix.sync.aligned.m8n8.x4.shared.b16 {%0,%1,%2,%3}, [%4];"
                 : "=r"(r[0]), "=r"(r[1]), "=r"(r[2]), "=r"(r[3]) : "r"(addr));
}
__device__ __forceinline__ void mma16816(float* c, const uint32_t* a, uint32_t b0, uint32_t b1) {
    asm volatile(
        "mma.sync.aligned.m16n8k16.row.col.f32.f16.f16.f32 "
        "{%0,%1,%2,%3}, {%4,%5,%6,%7}, {%8,%9}, {%0,%1,%2,%3};\n"
        : "+f"(c[0]), "+f"(c[1]), "+f"(c[2]), "+f"(c[3])
        : "r"(a[0]), "r"(a[1]), "r"(a[2]), "r"(a[3]), "r"(b0), "r"(b1));
}

__device__ __forceinline__ uint32_t packh(float a, float b) {
    __half ha = __float2half_rn(a), hb = __float2half_rn(b);
    return ((uint32_t)__half_as_ushort(hb) << 16) | (uint32_t)__half_as_ushort(ha);
}
__device__ __forceinline__ uint2 pack4h(float4 v) {
    uint2 hp;
    hp.x = packh(v.x, v.y);
    hp.y = packh(v.z, v.w);
    return hp;
}
__device__ __forceinline__ float4 h4_to_f4(uint2 u) {
    __half2 a = *(__half2*)&u.x, b = *(__half2*)&u.y;
    float2 fa = __half22float2(a), fb = __half22float2(b);
    return make_float4(fa.x, fa.y, fb.x, fb.y);
}

// ---------------- fused CSR build kernels (both graphs per launch) ----------------
__global__ void zero_both_kernel(int* __restrict__ p1, int* __restrict__ p2) {
    int i = blockIdx.x * blockDim.x + threadIdx.x;
    if (i < NWM) p1[i] = 0;
    else if (i < NWM + NF) p2[i - NWM] = 0;
}
__global__ void hist_both_kernel(const int* __restrict__ dstW, int* __restrict__ cntW,
                                 const int* __restrict__ dstF, int* __restrict__ cntF) {
    int e = blockIdx.x * blockDim.x + threadIdx.x;
    if (e < EWM) atomicAdd(&cntW[dstW[e]], 1);
    else if (e < EWM + EF) atomicAdd(&cntF[dstF[e - EWM]], 1);
}
// 2 blocks: block 0 -> WM, block 1 -> FSTM
__global__ void scan_both_kernel(int* __restrict__ cntW, int* __restrict__ rpW,
                                 int* __restrict__ cntF, int* __restrict__ rpF) {
    __shared__ int sh[1024];
    int* cnt_cur = blockIdx.x == 0 ? cntW : cntF;
    int* rowptr  = blockIdx.x == 0 ? rpW  : rpF;
    const int N  = blockIdx.x == 0 ? NWM : NF;
    const int E  = blockIdx.x == 0 ? EWM : EF;
    int tid = threadIdx.x;
    int chunk = (N + 1023) >> 10;
    int s0 = tid * chunk;
    int s1 = s0 + chunk; if (s1 > N) s1 = N;
    int s = 0;
    for (int i = s0; i < s1; i++) s += cnt_cur[i];
    sh[tid] = s;
    __syncthreads();
    for (int off = 1; off < 1024; off <<= 1) {
        int v = (tid >= off) ? sh[tid - off] : 0;
        __syncthreads();
        sh[tid] += v;
        __syncthreads();
    }
    int run = sh[tid] - s;
    for (int i = s0; i < s1; i++) {
        int c = cnt_cur[i];
        rowptr[i]  = run;
        cnt_cur[i] = run;
        run += c;
    }
    if (tid == 0) rowptr[N] = E;
}
__global__ void fill_both_kernel(const int* __restrict__ srcW, const int* __restrict__ dstW,
                                 int* __restrict__ curW, int* __restrict__ colW,
                                 const int* __restrict__ srcF, const int* __restrict__ dstF,
                                 int* __restrict__ curF, int* __restrict__ colF) {
    int e = blockIdx.x * blockDim.x + threadIdx.x;
    if (e < EWM) {
        int d = dstW[e];
        int p = atomicAdd(&curW[d], 1);
        colW[p] = srcW[e];
    } else if (e < EWM + EF) {
        int e2 = e - EWM;
        int d = dstF[e2];
        int p = atomicAdd(&curF[d], 1);
        colF[p] = srcF[e2];
    }
}

// ---------------- elementwise / gather kernels ----------------
__global__ void split_x_hi_kernel(const float4* __restrict__ x,
                                  __half* __restrict__ oh, int n4) {
    int idx = blockIdx.x * blockDim.x + threadIdx.x;
    if (idx >= n4) return;
    *(uint2*)(oh + 4 * (size_t)idx) = pack4h(x[idx]);
}

// fp16-t aggregation: v = relu(t[n] + sum t[src] + bias); write fp16 (strided)
__global__ void spmm_post_h16_kernel(const uint2* __restrict__ t,
                                     const int* __restrict__ rowptr,
                                     const int* __restrict__ col,
                                     const float* __restrict__ bias,
                                     __half* __restrict__ oh,
                                     size_t ldo, size_t coff, int n) {
    int node = blockIdx.x * blockDim.y + threadIdx.y;
    if (node >= n) return;
    int x = threadIdx.x;  // 0..63 (uint2 = 4 halves)
    float4 acc = h4_to_f4(t[(size_t)node * 64 + x]);
    int e  = rowptr[node];
    int e1 = rowptr[node + 1];
    for (; e + 4 <= e1; e += 4) {
        int s0 = __ldg(&col[e]), s1 = __ldg(&col[e + 1]);
        int s2 = __ldg(&col[e + 2]), s3 = __ldg(&col[e + 3]);
        float4 v0 = h4_to_f4(__ldg(&t[(size_t)s0 * 64 + x]));
        float4 v1 = h4_to_f4(__ldg(&t[(size_t)s1 * 64 + x]));
        float4 v2 = h4_to_f4(__ldg(&t[(size_t)s2 * 64 + x]));
        float4 v3 = h4_to_f4(__ldg(&t[(size_t)s3 * 64 + x]));
        acc.x += v0.x + v1.x + v2.x + v3.x;
        acc.y += v0.y + v1.y + v2.y + v3.y;
        acc.z += v0.z + v1.z + v2.z + v3.z;
        acc.w += v0.w + v1.w + v2.w + v3.w;
    }
    for (; e < e1; ++e) {
        int s = __ldg(&col[e]);
        float4 v = h4_to_f4(__ldg(&t[(size_t)s * 64 + x]));
        acc.x += v.x; acc.y += v.y; acc.z += v.z; acc.w += v.w;
    }
    float4 bv = *(const float4*)&bias[4 * x];
    acc.x = fmaxf(acc.x + bv.x, 0.f);
    acc.y = fmaxf(acc.y + bv.y, 0.f);
    acc.z = fmaxf(acc.z + bv.z, 0.f);
    acc.w = fmaxf(acc.w + bv.w, 0.f);
    *(uint2*)(oh + (size_t)node * ldo + coff + 4 * x) = pack4h(acc);
}

// tmp[row] = sum_k ge16[t2n[row*4+k]]; fp16 into cat1 @col0 and cat3 @col768
__global__ void gather4sum_h_kernel(const uint2* __restrict__ ge,
                                    const int* __restrict__ t2n,
                                    __half* __restrict__ c1h,
                                    __half* __restrict__ c3h, int rows) {
    int row = blockIdx.x * blockDim.y + threadIdx.y;
    if (row >= rows) return;
    int x = threadIdx.x;
    float4 acc = make_float4(0.f, 0.f, 0.f, 0.f);
#pragma unroll
    for (int k = 0; k < KSLOT; k++) {
        int idx = __ldg(&t2n[row * KSLOT + k]);
        float4 v = h4_to_f4(__ldg(&ge[(size_t)idx * 64 + x]));
        acc.x += v.x; acc.y += v.y; acc.z += v.z; acc.w += v.w;
    }
    uint2 hp = pack4h(acc);
    *(uint2*)(c1h + (size_t)row * CAT1 + 4 * x) = hp;
    *(uint2*)(c3h + (size_t)row * CAT3 + PLM + 4 * x) = hp;
}

// text fp32 -> fp16 into cat1 @col 256 and cat3 @col 0
__global__ void textconv_kernel(const float4* __restrict__ text,
                                __half* __restrict__ c1h,
                                __half* __restrict__ c3h, int rows) {
    int idx = blockIdx.x * blockDim.x + threadIdx.x;
    if (idx >= rows * PLM4) return;
    int row = idx / PLM4;
    int c   = idx - row * PLM4;
    uint2 hp = pack4h(text[idx]);
    *(uint2*)(c1h + (size_t)row * CAT1 + GG + 4 * c) = hp;
    *(uint2*)(c3h + (size_t)row * CAT3 + 4 * c) = hp;
}

// all weights [K,N] fp32 -> transposed [N,K] fp16 in ONE launch (grid.z selects)
struct WDesc { const float* W; __half* Wh; int Kd; int Nd; };
struct WDescPack { WDesc d[6]; };
__global__ void wconv_all_kernel(WDescPack pack) {
    __shared__ float t[32][33];
    const WDesc& w = pack.d[blockIdx.z];
    int kb = blockIdx.y * 32, nb = blockIdx.x * 32;
    if (kb >= w.Kd || nb >= w.Nd) return;
#pragma unroll
    for (int j = 0; j < 32; j += 8) {
        int k = kb + threadIdx.y + j, n = nb + threadIdx.x;
        t[threadIdx.y + j][threadIdx.x] = w.W[(size_t)k * w.Nd + n];
    }
    __syncthreads();
#pragma unroll
    for (int j = 0; j < 32; j += 8) {
        int n = nb + threadIdx.y + j, k = kb + threadIdx.x;
        w.Wh[(size_t)n * w.Kd + k] = __float2half_rn(t[threadIdx.x][threadIdx.y + j]);
    }
}

// ---------------- legacy-MMA fp16 GEMM (1-pass, 4-stage, 128x64 tile, 3 CTA/SM) ----------------
// HMMA hardware-rate-bound (~28% tensor ceiling); low reg/CTA config leaves RF headroom
// so memory-bound side kernels can co-execute.
#define RS      80
#define TILEA   (128 * RS)           // 10240
#define TILEB2  (64 * RS)            // 5120
#define STAGEB  (TILEA + TILEB2)     // 15360
#define NSTAGE  4
#define GEMM_SMEM (NSTAGE * STAGEB)  // 61440

__global__ __launch_bounds__(256, 3)
void mgemm_kernel(const __half* __restrict__ Ah,
                  const __half* __restrict__ Bh,
                  const float* __restrict__ bias,
                  float* __restrict__ Cf, __half* __restrict__ Ch,
                  const int* __restrict__ Aidx,
                  int ldc, int M, int N, int K) {
    extern __shared__ char smem[];
    const uint32_t sb = smem_u32(smem);
    const int tid = threadIdx.x, lane = tid & 31, wid = tid >> 5;
    const int wm = wid & 3, wn = wid >> 2;
    const int bm = blockIdx.y * 128, bn = blockIdx.x * 64;
    const int g = lane >> 2, tg = lane & 3;

    const int srow = tid >> 1;
    const int hsel = tid & 1;
    const int arow = bm + srow;
    const bool aok = arow < M;
    int arA = aok ? arow : 0;
    if (Aidx) arA = __ldg(&Aidx[arA]);
    const uint32_t asz = aok ? 16u : 0u;
    const int brow = bn + (srow & 63);
    const uint32_t adoff = srow * RS + hsel * 32;
    const uint32_t bdoff = (srow & 63) * RS + hsel * 32;

    auto stage = [&](int kt, int b) {
        const size_t ko = (size_t)kt * 32 + hsel * 16;
        const __half* pA = Ah + (size_t)arA * K + ko;
        const uint32_t abase = sb + b * STAGEB + adoff;
        cp16(abase,      pA,     asz);
        cp16(abase + 16, pA + 8, asz);
        if (tid < 128) {
            const __half* pB = Bh + (size_t)brow * K + ko;
            const uint32_t bbase = sb + b * STAGEB + TILEA + bdoff;
            cp16(bbase,      pB,     16u);
            cp16(bbase + 16, pB + 8, 16u);
        }
    };

    const uint32_t aro = (wm * 32 + (lane & 7) + ((lane >> 3) & 1) * 8) * RS;
    const uint32_t ako = ((lane >> 4) & 1) * 16;
    const uint32_t bro = (wn * 32 + (lane & 7) + ((lane >> 4) & 1) * 8) * RS;
    const uint32_t bko = ((lane >> 3) & 1) * 16;

    float acc[2][4][4];
#pragma unroll
    for (int i = 0; i < 2; i++)
#pragma unroll
        for (int j = 0; j < 4; j++)
#pragma unroll
            for (int q = 0; q < 4; q++) acc[i][j][q] = 0.f;

    const int nk = K >> 5;
    stage(0, 0); CP_COMMIT();
    stage(1, 1); CP_COMMIT();
    stage(2, 2); CP_COMMIT();

    int b = 0;
    for (int t = 0; t < nk; t++) {
        const int rem = nk - 1 - t;
        if (rem >= 2)      { CP_WAIT(2); }
        else if (rem == 1) { CP_WAIT(1); }
        else               { CP_WAIT(0); }
        __syncthreads();
        if (t + 3 < nk) {
            int nb3 = b + 3; if (nb3 >= NSTAGE) nb3 -= NSTAGE;
            stage(t + 3, nb3);
            CP_COMMIT();
        }

        const uint32_t baseA = sb + b * STAGEB;
        const uint32_t baseB = sb + b * STAGEB + TILEA;

#pragma unroll
        for (int s = 0; s < 2; s++) {
            const uint32_t kb = s * 32;
            uint32_t af[2][4], bf[4][2];
#pragma unroll
            for (int mt = 0; mt < 2; mt++)
                ldsm4(af[mt], baseA + aro + mt * (16 * RS) + kb + ako);
#pragma unroll
            for (int p = 0; p < 2; p++) {
                uint32_t r[4];
                ldsm4(r, baseB + bro + p * (16 * RS) + kb + bko);
                bf[2 * p][0] = r[0]; bf[2 * p][1] = r[1];
                bf[2 * p + 1][0] = r[2]; bf[2 * p + 1][1] = r[3];
            }
#pragma unroll
            for (int nt = 0; nt < 4; nt++)
#pragma unroll
                for (int mt = 0; mt < 2; mt++)
                    mma16816(acc[mt][nt], af[mt], bf[nt][0], bf[nt][1]);
        }
        if (++b == NSTAGE) b = 0;
    }

    // ---- epilogue ----
#pragma unroll
    for (int nt = 0; nt < 4; nt++) {
        const int col = bn + wn * 32 + nt * 8 + 2 * tg;
        float2 bv = *(const float2*)&bias[col];
#pragma unroll
        for (int mt = 0; mt < 2; mt++) {
            const int row0 = bm + wm * 32 + mt * 16 + g;
            float v0 = acc[mt][nt][0] + bv.x;
            float v1 = acc[mt][nt][1] + bv.y;
            float v2 = acc[mt][nt][2] + bv.x;
            float v3 = acc[mt][nt][3] + bv.y;
            if (Ch) {
                if (row0 < M)
                    *(uint32_t*)(Ch + (size_t)row0 * ldc + col) = packh(v0, v1);
                if (row0 + 8 < M)
                    *(uint32_t*)(Ch + (size_t)(row0 + 8) * ldc + col) = packh(v2, v3);
            } else {
                if (row0 < M)
                    *(float2*)&Cf[(size_t)row0 * ldc + col] = make_float2(v0, v1);
                if (row0 + 8 < M)
                    *(float2*)&Cf[(size_t)(row0 + 8) * ldc + col] = make_float2(v2, v3);
            }
        }
    }
}

// ---------------- host launcher ----------------
static void mgemm(const __half* Ah, const __half* Bh, const float* bias,
                  float* Cf, __half* Ch, const int* Aidx,
                  int ldc, int M, int N, int K) {
    dim3 grid(N / 64, (M + 127) / 128);
    mgemm_kernel<<<grid, 256, GEMM_SMEM>>>(Ah, Bh, bias, Cf, Ch, Aidx, ldc, M, N, K);
}

extern "C" void kernel_launch(void* const* d_in, const int* in_sizes, int n_in,
                              void* d_out, int out_size) {
    (void)in_sizes; (void)n_in; (void)out_size;

    const float* text   = (const float*)d_in[0];
    const float* wm_x   = (const float*)d_in[1];
    const int*   wm_ei  = (const int*)  d_in[2];
    const int*   t2n    = (const int*)  d_in[3];
    const int*   fids   = (const int*)  d_in[4];
    const int*   f_ei   = (const int*)  d_in[5];
    // d_in[6] extra_emb: unreachable (indices always >= 2)
    const float* wm_W1  = (const float*)d_in[7];
    const float* wm_b1  = (const float*)d_in[8];
    const float* wm_W2  = (const float*)d_in[9];
    const float* wm_b2  = (const float*)d_in[10];
    const float* f_W1   = (const float*)d_in[11];
    const float* f_b1   = (const float*)d_in[12];
    const float* f_W2   = (const float*)d_in[13];
    const float* f_b2   = (const float*)d_in[14];
    const float* fc1_W  = (const float*)d_in[15];
    const float* fc1_b  = (const float*)d_in[16];
    const float* fc3_W  = (const float*)d_in[17];
    const float* fc3_b  = (const float*)d_in[18];
    float* out = (float*)d_out;

    cudaFuncSetAttribute(mgemm_kernel, cudaFuncAttributeMaxDynamicSharedMemorySize, GEMM_SMEM);

    // one-time host objects (no device memory): side stream + fork/join events
    static cudaStream_t sSide = nullptr;
    static cudaEvent_t evRoot = nullptr, evCSR = nullptr, evTC = nullptr;
    if (!sSide) {
        cudaStreamCreateWithFlags(&sSide, cudaStreamNonBlocking);
        cudaEventCreateWithFlags(&evRoot, cudaEventDisableTiming);
        cudaEventCreateWithFlags(&evCSR,  cudaEventDisableTiming);
        cudaEventCreateWithFlags(&evTC,   cudaEventDisableTiming);
    }

    float* zb;
    __half *th, *geh, *ah, *gteh, *c1h, *c3h;
    __half *w1h, *w2h, *gh1, *gh2, *p1h, *p3h;
    int *wrp, *wcur, *wcol, *frp, *fcur, *fcol;
    cudaGetSymbolAddress((void**)&zb,   g_zerob);
    cudaGetSymbolAddress((void**)&th,   g_th);
    cudaGetSymbolAddress((void**)&geh,  g_geh);
    cudaGetSymbolAddress((void**)&ah,   g_ah);
    cudaGetSymbolAddress((void**)&gteh, g_gteh);
    cudaGetSymbolAddress((void**)&c1h,  g_c1h);
    cudaGetSymbolAddress((void**)&c3h,  g_c3h);
    cudaGetSymbolAddress((void**)&w1h,  g_w1h);
    cudaGetSymbolAddress((void**)&w2h,  g_w2h);
    cudaGetSymbolAddress((void**)&gh1,  g_g1h);
    cudaGetSymbolAddress((void**)&gh2,  g_g2h);
    cudaGetSymbolAddress((void**)&p1h,  g_fc1h);
    cudaGetSymbolAddress((void**)&p3h,  g_fc3h);
    cudaGetSymbolAddress((void**)&wrp,  g_wm_rowptr);
    cudaGetSymbolAddress((void**)&wcur, g_wm_cur);
    cudaGetSymbolAddress((void**)&wcol, g_wm_col);
    cudaGetSymbolAddress((void**)&frp,  g_f_rowptr);
    cudaGetSymbolAddress((void**)&fcur, g_f_cur);
    cudaGetSymbolAddress((void**)&fcol, g_f_col);

    const dim3 bSp(64, 4);

    // ===== fork side stream at capture root =====
    cudaEventRecord(evRoot, 0);
    cudaStreamWaitEvent(sSide, evRoot, 0);

    // ----- side stream: CSR build (both graphs) + textconv (input-only deps) -----
    zero_both_kernel<<<(NWM + NF + 255) / 256, 256, 0, sSide>>>(wcur, fcur);
    hist_both_kernel<<<(EWM + EF + 255) / 256, 256, 0, sSide>>>(wm_ei + EWM, wcur,
                                                                f_ei + EF, fcur);
    scan_both_kernel<<<2, 1024, 0, sSide>>>(wcur, wrp, fcur, frp);
    fill_both_kernel<<<(EWM + EF + 255) / 256, 256, 0, sSide>>>(wm_ei, wm_ei + EWM, wcur, wcol,
                                                                f_ei, f_ei + EF, fcur, fcol);
    cudaEventRecord(evCSR, sSide);
    textconv_kernel<<<(NF * PLM4 + 255) / 256, 256, 0, sSide>>>((const float4*)text, c1h, c3h, NF);
    cudaEventRecord(evTC, sSide);

    // ----- main stream: WM GEMM chain -----
    split_x_hi_kernel<<<(NWM * G4 + 255) / 256, 256>>>((const float4*)wm_x, ah, NWM * G4);
    {
        WDescPack pack;
        pack.d[0] = { wm_W1, w1h, GG,   GG  };
        pack.d[1] = { wm_W2, w2h, GG,   GG  };
        pack.d[2] = { f_W1,  gh1, GG,   GG  };
        pack.d[3] = { f_W2,  gh2, GG,   GG  };
        pack.d[4] = { fc1_W, p1h, CAT1, GG  };
        pack.d[5] = { fc3_W, p3h, CAT3, PLM };
        wconv_all_kernel<<<dim3(PLM / 32, CAT3 / 32, 6), dim3(32, 8)>>>(pack);
    }
    mgemm(ah, w1h, zb, nullptr, th, nullptr, GG, NWM, GG, GG);
    cudaStreamWaitEvent(0, evCSR, 0);   // join: aggregation needs CSR
    spmm_post_h16_kernel<<<(NWM + 3) / 4, bSp>>>((const uint2*)th, wrp, wcol, wm_b1,
                                                 ah, GG, 0, NWM);
    mgemm(ah, w2h, zb, nullptr, th, nullptr, GG, NWM, GG, GG);
    spmm_post_h16_kernel<<<(NWM + 3) / 4, bSp>>>((const uint2*)th, wrp, wcol, wm_b2,
                                                 geh, GG, 0, NWM);
    // geh = graph_embeddings [NWM, G] fp16

    // ===== token concept sum -> cat buffers =====
    gather4sum_h_kernel<<<(NF + 3) / 4, bSp>>>((const uint2*)geh, t2n, c1h, c3h, NF);
    cudaStreamWaitEvent(0, evTC, 0);    // join: fc1 needs textconv columns

    // ===== fc1 =====
    mgemm(c1h, p1h, fc1_b, nullptr, gteh, nullptr, GG, NF, GG, CAT1);

    // ===== FSTM layer 1 (A gathered via fids inside GEMM) =====
    mgemm(gteh, gh1, zb, nullptr, th, fids, GG, NF, GG, GG);
    spmm_post_h16_kernel<<<(NF + 3) / 4, bSp>>>((const uint2*)th, frp, fcol, f_b1,
                                                ah, GG, 0, NF);
    // ===== FSTM layer 2 (output straight into cat3 @ col 1024) =====
    mgemm(ah, gh2, zb, nullptr, th, nullptr, GG, NF, GG, GG);
    spmm_post_h16_kernel<<<(NF + 3) / 4, bSp>>>((const uint2*)th, frp, fcol, f_b2,
                                                c3h, CAT3, PLM + GG, NF);

    // ===== fc3 -> out =====
    mgemm(c3h, p3h, fc3_b, out, nullptr, nullptr, PLM, NF, PLM, CAT3);
}